// round 5
// baseline (speedup 1.0000x reference)
#include <cuda_runtime.h>

// 8x8 IDCT: separable + even/odd symmetry, FOUR block-rows per thread (MLP=8),
// all global access 128-bit with streaming cache hints.
//   out = 0.25 * M^T * S * M + 128,  M[y][v] = a[y]*cos((2v+1)*y*pi/16)
// R4 lesson: DRAM pinned at ~71% with issue 61% = shfl-latency exposure.
// This version front-batches 8 independent LDG.128 and runs 4 independent
// transpose/math chains per thread to bury the shuffle latency.

#define FULLMASK 0xFFFFFFFFu

__device__ __forceinline__ void transpose8(float v[8], int r) {
    // 8x8 transpose across an 8-lane group, one row per lane; 3 bfly stages.
#pragma unroll
    for (int m = 1; m < 8; m <<= 1) {
#pragma unroll
        for (int i = 0; i < 8; i++) {
            if (i & m) continue;
            const int j = i | m;
            const bool up = (r & m) != 0;
            float send = up ? v[i] : v[j];
            float recv = __shfl_xor_sync(FULLMASK, send, m);
            if (up) v[i] = recv; else v[j] = recv;
        }
    }
}

// Even rows of M (y=0,2,4,6) and odd rows (y=1,3,5,7), columns v=0..3.
#define ME_ROWS \
    { 0.70710678f,  0.70710678f,  0.70710678f,  0.70710678f }, \
    { 0.92387953f,  0.38268343f, -0.38268343f, -0.92387953f }, \
    { 0.70710678f, -0.70710678f, -0.70710678f,  0.70710678f }, \
    { 0.38268343f, -0.92387953f,  0.92387953f, -0.38268343f }
#define MO_ROWS \
    { 0.98078528f,  0.83146961f,  0.55557023f,  0.19509032f }, \
    { 0.83146961f, -0.19509032f, -0.98078528f, -0.55557023f }, \
    { 0.55557023f, -0.98078528f,  0.19509032f,  0.83146961f }, \
    { 0.19509032f, -0.55557023f,  0.83146961f, -0.98078528f }

__device__ __forceinline__ void idct_row_pass(const float s[8], float acc[8]) {
    const float ME[4][4] = { ME_ROWS };
    const float MO[4][4] = { MO_ROWS };
#pragma unroll
    for (int v = 0; v < 4; v++) {
        float e = s[0] * ME[0][v];
        e = fmaf(s[2], ME[1][v], e);
        e = fmaf(s[4], ME[2][v], e);
        e = fmaf(s[6], ME[3][v], e);
        float o = s[1] * MO[0][v];
        o = fmaf(s[3], MO[1][v], o);
        o = fmaf(s[5], MO[2][v], o);
        o = fmaf(s[7], MO[3][v], o);
        acc[v]     = e + o;
        acc[7 - v] = e - o;
    }
}

__device__ __forceinline__ void idct_col_pass(const float acc[8], float o[8]) {
    const float ME[4][4] = { ME_ROWS };
    const float MO[4][4] = { MO_ROWS };
#pragma unroll
    for (int u = 0; u < 4; u++) {
        float e = fmaf(acc[0], 0.25f * ME[0][u], 128.0f);
        e = fmaf(acc[2], 0.25f * ME[1][u], e);
        e = fmaf(acc[4], 0.25f * ME[2][u], e);
        e = fmaf(acc[6], 0.25f * ME[3][u], e);
        float od = acc[1] * (0.25f * MO[0][u]);
        od = fmaf(acc[3], 0.25f * MO[1][u], od);
        od = fmaf(acc[5], 0.25f * MO[2][u], od);
        od = fmaf(acc[7], 0.25f * MO[3][u], od);
        o[u]     = e + od;
        o[7 - u] = e - od;
    }
}

__global__ void __launch_bounds__(256)
idct_54271206752953_kernel(const float* __restrict__ in,
                           float* __restrict__ out,
                           int n_rows) {
    const int tid = threadIdx.x;
    const int r = tid & 7;
    // Each 256-thread block owns 1024 consecutive 8-float rows.
    const int base = blockIdx.x * 1024;

    const float4* in4 = reinterpret_cast<const float4*>(in);
    float4* out4 = reinterpret_cast<float4*>(out);

    // Front-batch 8 independent LDG.128 (MLP_p1 = 8), streaming hint.
    float4 ld[4][2];
#pragma unroll
    for (int k = 0; k < 4; k++) {
        const size_t t = (size_t)(base + k * 256 + tid) * 2;
        ld[k][0] = __ldcs(&in4[t + 0]);
        ld[k][1] = __ldcs(&in4[t + 1]);
    }

    // Four independent math+transpose chains.
    float v[4][8];
#pragma unroll
    for (int k = 0; k < 4; k++) {
        float s[8] = { ld[k][0].x, ld[k][0].y, ld[k][0].z, ld[k][0].w,
                       ld[k][1].x, ld[k][1].y, ld[k][1].z, ld[k][1].w };
        idct_row_pass(s, v[k]);
    }
#pragma unroll
    for (int k = 0; k < 4; k++) transpose8(v[k], r);

#pragma unroll
    for (int k = 0; k < 4; k++) {
        float o[8];
        idct_col_pass(v[k], o);
#pragma unroll
        for (int i = 0; i < 8; i++) v[k][i] = o[i];
    }
#pragma unroll
    for (int k = 0; k < 4; k++) transpose8(v[k], r);

    // Row-major 128-bit streaming stores.
#pragma unroll
    for (int k = 0; k < 4; k++) {
        const size_t t = (size_t)(base + k * 256 + tid) * 2;
        __stcs(&out4[t + 0], make_float4(v[k][0], v[k][1], v[k][2], v[k][3]));
        __stcs(&out4[t + 1], make_float4(v[k][4], v[k][5], v[k][6], v[k][7]));
    }
}

extern "C" void kernel_launch(void* const* d_in, const int* in_sizes, int n_in,
                              void* d_out, int out_size) {
    const float* images = (const float*)d_in[0];
    float* out = (float*)d_out;
    const int n_rows = in_sizes[0] / 8;      // 4,194,304 for the bench shape
    const int blocks = n_rows / 1024;        // 1024 rows per 256-thread block
    idct_54271206752953_kernel<<<blocks, 256>>>(images, out, n_rows);
}